// round 1
// baseline (speedup 1.0000x reference)
#include <cuda_runtime.h>

#define LPn 4096
#define LHn 4096
#define Dn 300
#define Hn 512

// ---------------- scratch (device globals; no allocation allowed) ----------
__device__ float g_pemb[LPn * Dn];
__device__ float g_hemb[LHn * Dn];
__device__ float g_fp[LPn * Hn];
__device__ float g_fh[LHn * Hn];
__device__ float g_t1[LPn * Hn];
__device__ float g_t2[LPn * Hn];
__device__ float g_cat[LPn * 2 * Dn];
__device__ float g_eik[LPn];
__device__ float g_ekj[LHn];
__device__ float g_v[2 * Hn];

// ---------------- small kernels -------------------------------------------
__global__ void gather_k(const int* __restrict__ idx, const float* __restrict__ emb,
                         float* __restrict__ dst, int n) {
    int t = blockIdx.x * blockDim.x + threadIdx.x;
    if (t < n) {
        int r = t / Dn, c = t - r * Dn;
        dst[t] = emb[(long)idx[r] * Dn + c];
    }
}

__global__ void zero_k() {
    int t = blockIdx.x * blockDim.x + threadIdx.x;
    if (t < LHn) g_ekj[t] = 0.f;
    if (t < 2 * Hn) g_v[t] = 0.f;
}

__global__ void rowsum_k(const float* __restrict__ E, float* __restrict__ out) {
    int row = blockIdx.x * (blockDim.x / 32) + (threadIdx.x >> 5);
    int lane = threadIdx.x & 31;
    const float* p = E + (long)row * LHn;
    float s = 0.f;
    for (int j = lane; j < LHn; j += 32) s += p[j];
    #pragma unroll
    for (int o = 16; o; o >>= 1) s += __shfl_xor_sync(0xffffffffu, s, o);
    if (lane == 0) out[row] = s;
}

// partial column sums with atomic accumulation (out must be pre-zeroed)
__global__ void colsum_acc_k(const float* __restrict__ X, float* __restrict__ out,
                             int rows, int cols, int rows_per_blk) {
    int col = blockIdx.x * blockDim.x + threadIdx.x;
    if (col >= cols) return;
    int r0 = blockIdx.y * rows_per_blk;
    float s = 0.f;
    for (int r = r0; r < r0 + rows_per_blk; r++) s += X[(long)r * cols + col];
    atomicAdd(&out[col], s);
}

__global__ void concat_k(const float* __restrict__ a, const float* __restrict__ b,
                         float* __restrict__ dst, int n) {  // n = rows*600
    int t = blockIdx.x * blockDim.x + threadIdx.x;
    if (t < n) {
        int r = t / (2 * Dn), c = t - r * (2 * Dn);
        dst[t] = (c < Dn) ? a[r * Dn + c] : b[r * Dn + (c - Dn)];
    }
}

// ---------------- tiled fp32 GEMM -----------------------------------------
// C[M,N] = op( A @ B ) ; A logical [M,K] (A_T: Aphys[k*lda+m]), B logical [K,N]
// B_WT: B stored as W[N,K] row-major (B[k,n] = W[n*ldb+k]); else B[k*ldb+n].
// SCALE==1: C row m scaled by 1/scale[m].
template <bool A_T, bool B_WT, bool RELU, bool BIAS, int SCALE>
__global__ void gemm64(const float* __restrict__ A, int lda,
                       const float* __restrict__ B, int ldb,
                       const float* __restrict__ bias,
                       const float* __restrict__ scale,
                       float* __restrict__ C, int ldc,
                       int M, int N, int K) {
    const int BM = 64, BN = 64, BK = 16;
    __shared__ float As[BK][BM];
    __shared__ float Bs[BK][BN];
    int bm = blockIdx.y * BM, bn = blockIdx.x * BN;
    int tid = threadIdx.x;
    int tx = tid & 15, ty = tid >> 4;

    float acc[4][4];
    #pragma unroll
    for (int i = 0; i < 4; i++)
        #pragma unroll
        for (int j = 0; j < 4; j++) acc[i][j] = 0.f;

    for (int k0 = 0; k0 < K; k0 += BK) {
        if (!A_T) {
            int kk = tid & 15, mm = tid >> 4;
            #pragma unroll
            for (int r = 0; r < 4; r++) {
                int m = mm + r * 16;
                int gm = bm + m, gk = k0 + kk;
                As[kk][m] = (gm < M && gk < K) ? A[(long)gm * lda + gk] : 0.f;
            }
        } else {
            int mm = tid & 63, kk = tid >> 6;
            #pragma unroll
            for (int r = 0; r < 4; r++) {
                int k = kk + r * 4;
                int gm = bm + mm, gk = k0 + k;
                As[k][mm] = (gm < M && gk < K) ? A[(long)gk * lda + gm] : 0.f;
            }
        }
        if (B_WT) {
            int kk = tid & 15, nn = tid >> 4;
            #pragma unroll
            for (int r = 0; r < 4; r++) {
                int n = nn + r * 16;
                int gn = bn + n, gk = k0 + kk;
                Bs[kk][n] = (gn < N && gk < K) ? B[(long)gn * ldb + gk] : 0.f;
            }
        } else {
            int nn = tid & 63, kk = tid >> 6;
            #pragma unroll
            for (int r = 0; r < 4; r++) {
                int k = kk + r * 4;
                int gn = bn + nn, gk = k0 + k;
                Bs[k][nn] = (gn < N && gk < K) ? B[(long)gk * ldb + gn] : 0.f;
            }
        }
        __syncthreads();
        #pragma unroll
        for (int k = 0; k < BK; k++) {
            float a[4], b[4];
            #pragma unroll
            for (int i = 0; i < 4; i++) a[i] = As[k][ty + i * 16];
            #pragma unroll
            for (int j = 0; j < 4; j++) b[j] = Bs[k][tx + j * 16];
            #pragma unroll
            for (int i = 0; i < 4; i++)
                #pragma unroll
                for (int j = 0; j < 4; j++) acc[i][j] += a[i] * b[j];
        }
        __syncthreads();
    }

    #pragma unroll
    for (int i = 0; i < 4; i++) {
        int row = bm + ty + i * 16;
        if (row >= M) continue;
        float s = 1.f;
        if (SCALE == 1) s = 1.f / scale[row];
        #pragma unroll
        for (int j = 0; j < 4; j++) {
            int col = bn + tx + j * 16;
            if (col >= N) continue;
            float v = acc[i][j];
            if (BIAS) v += bias[col];
            if (SCALE == 1) v *= s;
            if (RELU) v = fmaxf(v, 0.f);
            C[(long)row * ldc + col] = v;
        }
    }
}

// ---------------- final tiny MLP + softmax --------------------------------
__global__ void final_k(const float* __restrict__ Wg1, const float* __restrict__ bg1,
                        const float* __restrict__ Wg2, const float* __restrict__ bg2,
                        const float* __restrict__ Wg3, const float* __restrict__ bg3,
                        float* __restrict__ outv, float* __restrict__ outy) {
    __shared__ float vcat[2 * Hn];
    __shared__ float y1[Hn];
    __shared__ float y2[Hn];
    int t = threadIdx.x;  // 1024 threads
    vcat[t] = g_v[t];
    outv[t] = g_v[t];
    __syncthreads();
    if (t < Hn) {
        float s = bg1[t];
        for (int k = 0; k < 2 * Hn; k++) s += vcat[k] * Wg1[t * 2 * Hn + k];
        y1[t] = fmaxf(s, 0.f);
    }
    __syncthreads();
    if (t < Hn) {
        float s = bg2[t];
        for (int k = 0; k < Hn; k++) s += y1[k] * Wg2[t * Hn + k];
        y2[t] = fmaxf(s, 0.f);
    }
    __syncthreads();
    if (t == 0) {
        float z[3];
        float mx = -1e30f;
        for (int c = 0; c < 3; c++) {
            float s = bg3[c];
            for (int k = 0; k < Hn; k++) s += y2[k] * Wg3[c * Hn + k];
            z[c] = s;
            mx = fmaxf(mx, z[c]);
        }
        float se = 0.f;
        for (int c = 0; c < 3; c++) { z[c] = expf(z[c] - mx); se += z[c]; }
        for (int c = 0; c < 3; c++) outy[c] = z[c] / se;
    }
}

// ---------------- launch --------------------------------------------------
extern "C" void kernel_launch(void* const* d_in, const int* in_sizes, int n_in,
                              void* d_out, int out_size) {
    const int*   p_idx = (const int*)d_in[0];
    const int*   h_idx = (const int*)d_in[1];
    const float* emb   = (const float*)d_in[2];
    const float* W_a1  = (const float*)d_in[3];
    const float* b_a1  = (const float*)d_in[4];
    const float* W_a2  = (const float*)d_in[5];
    const float* b_a2  = (const float*)d_in[6];
    const float* W_c1  = (const float*)d_in[7];
    const float* b_c1  = (const float*)d_in[8];
    const float* W_c2  = (const float*)d_in[9];
    const float* b_c2  = (const float*)d_in[10];
    const float* W_g1  = (const float*)d_in[11];
    const float* b_g1  = (const float*)d_in[12];
    const float* W_g2  = (const float*)d_in[13];
    const float* b_g2  = (const float*)d_in[14];
    const float* W_g3  = (const float*)d_in[15];
    const float* b_g3  = (const float*)d_in[16];

    float* out      = (float*)d_out;
    float* outE     = out;                        // [4096,4096]
    float* outBeta  = outE + (long)LPn * LHn;     // [4096,300]
    float* outAlpha = outBeta + (long)LPn * Dn;   // [4096,300]
    float* outV     = outAlpha + (long)LHn * Dn;  // [1024] = v1|v2
    float* outY     = outV + 2 * Hn;              // [3]

    float *pemb, *hemb, *fp, *fh, *t1, *t2, *cat, *eik, *ekj, *v;
    cudaGetSymbolAddress((void**)&pemb, g_pemb);
    cudaGetSymbolAddress((void**)&hemb, g_hemb);
    cudaGetSymbolAddress((void**)&fp, g_fp);
    cudaGetSymbolAddress((void**)&fh, g_fh);
    cudaGetSymbolAddress((void**)&t1, g_t1);
    cudaGetSymbolAddress((void**)&t2, g_t2);
    cudaGetSymbolAddress((void**)&cat, g_cat);
    cudaGetSymbolAddress((void**)&eik, g_eik);
    cudaGetSymbolAddress((void**)&ekj, g_ekj);
    cudaGetSymbolAddress((void**)&v, g_v);

    const int TB = 256;

    // gathers + zero accumulators
    gather_k<<<(LPn * Dn + TB - 1) / TB, TB>>>(p_idx, emb, pemb, LPn * Dn);
    gather_k<<<(LHn * Dn + TB - 1) / TB, TB>>>(h_idx, emb, hemb, LHn * Dn);
    zero_k<<<16, 256>>>();

    // attend(p): t1 = relu(pemb @ Wa1^T + b), fp = relu(t1 @ Wa2^T + b)
    gemm64<false, true, true, true, 0><<<dim3(Hn / 64, LPn / 64), TB>>>(
        pemb, Dn, W_a1, Dn, b_a1, nullptr, t1, Hn, LPn, Hn, Dn);
    gemm64<false, true, true, true, 0><<<dim3(Hn / 64, LPn / 64), TB>>>(
        t1, Hn, W_a2, Hn, b_a2, nullptr, fp, Hn, LPn, Hn, Hn);

    // attend(h)
    gemm64<false, true, true, true, 0><<<dim3(Hn / 64, LHn / 64), TB>>>(
        hemb, Dn, W_a1, Dn, b_a1, nullptr, t1, Hn, LHn, Hn, Dn);
    gemm64<false, true, true, true, 0><<<dim3(Hn / 64, LHn / 64), TB>>>(
        t1, Hn, W_a2, Hn, b_a2, nullptr, fh, Hn, LHn, Hn, Hn);

    // E = fp @ reshape(fh, [H, LH])  (row-major reinterpret => plain NN GEMM)
    gemm64<false, false, false, false, 0><<<dim3(LHn / 64, LPn / 64), TB>>>(
        fp, Hn, fh, LHn, nullptr, nullptr, outE, LHn, LPn, LHn, Hn);

    // eik (row sums), ekj (col sums)
    rowsum_k<<<LPn / 8, 256>>>(outE, eik);
    colsum_acc_k<<<dim3(LHn / 256, 32), 256>>>(outE, ekj, LPn, LHn, LPn / 32);

    // beta = (E / eik) @ hemb   [4096,300]
    gemm64<false, false, false, false, 1><<<dim3((Dn + 63) / 64, LPn / 64), TB>>>(
        outE, LHn, hemb, Dn, nullptr, eik, outBeta, Dn, LPn, Dn, LHn);

    // alpha = (E / ekj)^T @ pemb   [4096,300]  (TN gemm, per-row 1/ekj)
    gemm64<true, false, false, false, 1><<<dim3((Dn + 63) / 64, LHn / 64), TB>>>(
        outE, LHn, pemb, Dn, nullptr, ekj, outAlpha, Dn, LHn, Dn, LPn);

    // comp(p): cat(pemb, beta) -> 2 gemms -> column-sum into v1
    concat_k<<<(LPn * 2 * Dn + TB - 1) / TB, TB>>>(pemb, outBeta, cat, LPn * 2 * Dn);
    gemm64<false, true, true, true, 0><<<dim3(Hn / 64, LPn / 64), TB>>>(
        cat, 2 * Dn, W_c1, 2 * Dn, b_c1, nullptr, t1, Hn, LPn, Hn, 2 * Dn);
    gemm64<false, true, true, true, 0><<<dim3(Hn / 64, LPn / 64), TB>>>(
        t1, Hn, W_c2, Hn, b_c2, nullptr, t2, Hn, LPn, Hn, Hn);
    colsum_acc_k<<<dim3(Hn / 256, 32), 256>>>(t2, v, LPn, Hn, LPn / 32);

    // comp(h): cat(hemb, alpha) -> 2 gemms -> column-sum into v2
    concat_k<<<(LHn * 2 * Dn + TB - 1) / TB, TB>>>(hemb, outAlpha, cat, LHn * 2 * Dn);
    gemm64<false, true, true, true, 0><<<dim3(Hn / 64, LHn / 64), TB>>>(
        cat, 2 * Dn, W_c1, 2 * Dn, b_c1, nullptr, t1, Hn, LHn, Hn, 2 * Dn);
    gemm64<false, true, true, true, 0><<<dim3(Hn / 64, LHn / 64), TB>>>(
        t1, Hn, W_c2, Hn, b_c2, nullptr, t2, Hn, LHn, Hn, Hn);
    colsum_acc_k<<<dim3(Hn / 256, 32), 256>>>(t2, v + Hn, LHn, Hn, LHn / 32);

    // final head: writes v1,v2 and softmax y
    final_k<<<1, 1024>>>(W_g1, b_g1, W_g2, b_g2, W_g3, b_g3, outV, outY);
}

// round 2
// speedup vs baseline: 1.6083x; 1.6083x over previous
#include <cuda_runtime.h>

#define LPn 4096
#define LHn 4096
#define Dn 300
#define Hn 512
#define NSPLIT 8

// ---------------- scratch (device globals; no allocation allowed) ----------
__device__ float g_emb[(LPn + LHn) * Dn];     // p rows then h rows
__device__ float g_t1[(LPn + LHn) * Hn];
__device__ float g_fa[(LPn + LHn) * Hn];      // attend out: fp | fh
__device__ float g_t2[(LPn + LHn) * Hn];
__device__ float g_cat[(LPn + LHn) * 2 * Dn];
__device__ float g_part[NSPLIT * LPn * Dn];   // split-K partials
__device__ float g_eik[LPn];
__device__ float g_ekj[LHn];
__device__ float g_v[2 * Hn];

// ---------------- f32x2 packed FMA helpers --------------------------------
__device__ __forceinline__ void ffma2(unsigned long long& d, unsigned long long a,
                                      unsigned long long b) {
    asm("fma.rn.f32x2 %0, %1, %2, %0;" : "+l"(d) : "l"(a), "l"(b));
}
union U64F2 { unsigned long long u; float2 f; };

// ---------------- small kernels -------------------------------------------
__global__ void gather4_k(const int* __restrict__ idx, const float* __restrict__ emb,
                          float* __restrict__ dst, int rows) {
    int t = blockIdx.x * blockDim.x + threadIdx.x;  // rows * 75 float4s
    if (t < rows * (Dn / 4)) {
        int r = t / (Dn / 4), c = t - r * (Dn / 4);
        ((float4*)dst)[t] = ((const float4*)(emb + (size_t)idx[r] * Dn))[c];
    }
}

__global__ void zero_k() {
    int t = blockIdx.x * blockDim.x + threadIdx.x;
    if (t < LHn) g_ekj[t] = 0.f;
    if (t < 2 * Hn) g_v[t] = 0.f;
}

__global__ void rowsum_k(const float* __restrict__ E, float* __restrict__ out) {
    int row = blockIdx.x * (blockDim.x / 32) + (threadIdx.x >> 5);
    int lane = threadIdx.x & 31;
    const float4* p = (const float4*)(E + (size_t)row * LHn);
    float s = 0.f;
    for (int j = lane; j < LHn / 4; j += 32) {
        float4 v = p[j];
        s += (v.x + v.y) + (v.z + v.w);
    }
    #pragma unroll
    for (int o = 16; o; o >>= 1) s += __shfl_xor_sync(0xffffffffu, s, o);
    if (lane == 0) out[row] = s;
}

// partial column sums with atomic accumulation (out pre-zeroed)
__global__ void colsum_acc_k(const float* __restrict__ X, float* __restrict__ out,
                             int cols, int rows_per_blk) {
    int col = blockIdx.x * blockDim.x + threadIdx.x;
    if (col >= cols) return;
    long r0 = (long)blockIdx.y * rows_per_blk;
    float s = 0.f;
    for (long r = r0; r < r0 + rows_per_blk; r++) s += X[r * cols + col];
    atomicAdd(&out[col], s);
}

// cat rows: [emb_row | (beta or alpha) row]
__global__ void concat_k(const float* __restrict__ beta, const float* __restrict__ alpha,
                         float* __restrict__ dst) {
    int t = blockIdx.x * blockDim.x + threadIdx.x;  // 8192 * 150 float4
    if (t >= (LPn + LHn) * (2 * Dn / 4)) return;
    int R = t / (2 * Dn / 4), c4 = t - R * (2 * Dn / 4);
    float4 v;
    if (c4 < Dn / 4) {
        v = ((const float4*)(g_emb + (size_t)R * Dn))[c4];
    } else {
        const float* src = (R < LPn) ? (beta + (size_t)R * Dn)
                                     : (alpha + (size_t)(R - LPn) * Dn);
        v = ((const float4*)src)[c4 - Dn / 4];
    }
    ((float4*)dst)[t] = v;
}

// sum NSPLIT partials, scale rows by 1/scale[row]
__global__ void reduce_scale_k(const float* __restrict__ part,
                               const float* __restrict__ scale,
                               float* __restrict__ out, int M, int N) {
    int t = blockIdx.x * blockDim.x + threadIdx.x;  // over M*N/4
    if (t >= M * N / 4) return;
    float4 s = make_float4(0.f, 0.f, 0.f, 0.f);
    #pragma unroll
    for (int z = 0; z < NSPLIT; z++) {
        float4 v = ((const float4*)(part + (size_t)z * M * N))[t];
        s.x += v.x; s.y += v.y; s.z += v.z; s.w += v.w;
    }
    int row = (t * 4) / N;
    float r = 1.f / scale[row];
    s.x *= r; s.y *= r; s.z *= r; s.w *= r;
    ((float4*)out)[t] = s;
}

// ---------------- 128x128x8 f32x2 GEMM ------------------------------------
// C[M,N] = A@B. A logical [M,K]; A_T: Aphys[k*lda+m].
// B_WT: B = W[N,K] row-major (B[k,n]=W[n*ldb+k]); else B[k*ldb+n].
// SPLITK: blockIdx.z selects k range [z*Ksub, (z+1)*Ksub), C += z*M*ldc.
template <bool A_T, bool B_WT, bool RELU, bool BIAS, bool SPLITK>
__global__ void __launch_bounds__(256, 2)
sgemm128(const float* __restrict__ A, int lda,
         const float* __restrict__ B, int ldb,
         const float* __restrict__ bias,
         float* __restrict__ C, int ldc,
         int M, int N, int K, int Ksub) {
    __shared__ float As[8][256];  // duplicated pairs: As[k][2m]==As[k][2m+1]
    __shared__ float Bs[8][128];

    const int tid = threadIdx.x;
    const int tx = tid & 15, ty = tid >> 4;
    const int bm = blockIdx.y * 128, bn = blockIdx.x * 128;

    int k_off = 0, Kloc = K;
    if (SPLITK) {
        k_off = blockIdx.z * Ksub;
        Kloc = Ksub;
        C += (size_t)blockIdx.z * M * ldc;
    }
    const int kend = k_off + Kloc;

    unsigned long long acc[8][4];
    #pragma unroll
    for (int i = 0; i < 8; i++)
        #pragma unroll
        for (int j = 0; j < 4; j++) acc[i][j] = 0ull;

    for (int k0 = 0; k0 < Kloc; k0 += 8) {
        // ---- load A tile (duplicated) ----
        if (!A_T) {
            int m = tid & 127, kk = (tid >> 7) << 2;
            int gm = bm + m, gk = k_off + k0 + kk;
            float av[4] = {0.f, 0.f, 0.f, 0.f};
            if (gm < M) {
                if (gk + 3 < kend) {
                    float4 v = *(const float4*)(A + (size_t)gm * lda + gk);
                    av[0] = v.x; av[1] = v.y; av[2] = v.z; av[3] = v.w;
                } else {
                    #pragma unroll
                    for (int i = 0; i < 4; i++)
                        if (gk + i < kend) av[i] = A[(size_t)gm * lda + gk + i];
                }
            }
            #pragma unroll
            for (int i = 0; i < 4; i++) {
                As[kk + i][2 * m] = av[i];
                As[kk + i][2 * m + 1] = av[i];
            }
        } else {
            int kk = tid >> 5, m4 = (tid & 31) << 2;
            int gk = k_off + k0 + kk, gm = bm + m4;
            float av[4] = {0.f, 0.f, 0.f, 0.f};
            if (gk < kend) {
                if (gm + 3 < M) {
                    float4 v = *(const float4*)(A + (size_t)gk * lda + gm);
                    av[0] = v.x; av[1] = v.y; av[2] = v.z; av[3] = v.w;
                } else {
                    #pragma unroll
                    for (int i = 0; i < 4; i++)
                        if (gm + i < M) av[i] = A[(size_t)gk * lda + gm + i];
                }
            }
            #pragma unroll
            for (int i = 0; i < 4; i++) {
                As[kk][2 * (m4 + i)] = av[i];
                As[kk][2 * (m4 + i) + 1] = av[i];
            }
        }
        // ---- load B tile ----
        if (B_WT) {
            int n = tid >> 1, kk = (tid & 1) << 2;
            int gn = bn + n, gk = k_off + k0 + kk;
            float bv[4] = {0.f, 0.f, 0.f, 0.f};
            if (gn < N) {
                if (gk + 3 < kend) {
                    float4 v = *(const float4*)(B + (size_t)gn * ldb + gk);
                    bv[0] = v.x; bv[1] = v.y; bv[2] = v.z; bv[3] = v.w;
                } else {
                    #pragma unroll
                    for (int i = 0; i < 4; i++)
                        if (gk + i < kend) bv[i] = B[(size_t)gn * ldb + gk + i];
                }
            }
            #pragma unroll
            for (int i = 0; i < 4; i++) Bs[kk + i][n] = bv[i];
        } else {
            int kk = tid >> 5, n4 = (tid & 31) << 2;
            int gk = k_off + k0 + kk, gn = bn + n4;
            float4 v = make_float4(0.f, 0.f, 0.f, 0.f);
            if (gk < kend) {
                if (gn + 3 < N) {
                    v = *(const float4*)(B + (size_t)gk * ldb + gn);
                } else {
                    float tmp[4] = {0.f, 0.f, 0.f, 0.f};
                    #pragma unroll
                    for (int i = 0; i < 4; i++)
                        if (gn + i < N) tmp[i] = B[(size_t)gk * ldb + gn + i];
                    v = make_float4(tmp[0], tmp[1], tmp[2], tmp[3]);
                }
            }
            *(float4*)&Bs[kk][n4] = v;
        }
        __syncthreads();

        #pragma unroll
        for (int k = 0; k < 8; k++) {
            unsigned long long aa[8], bb[4];
            #pragma unroll
            for (int i = 0; i < 4; i++) {
                aa[i]     = *(const unsigned long long*)&As[k][2 * (ty * 4 + i)];
                aa[4 + i] = *(const unsigned long long*)&As[k][2 * (64 + ty * 4 + i)];
            }
            bb[0] = *(const unsigned long long*)&Bs[k][tx * 4];
            bb[1] = *(const unsigned long long*)&Bs[k][tx * 4 + 2];
            bb[2] = *(const unsigned long long*)&Bs[k][64 + tx * 4];
            bb[3] = *(const unsigned long long*)&Bs[k][64 + tx * 4 + 2];
            #pragma unroll
            for (int i = 0; i < 8; i++)
                #pragma unroll
                for (int j = 0; j < 4; j++) ffma2(acc[i][j], aa[i], bb[j]);
        }
        __syncthreads();
    }

    // ---- epilogue ----
    #pragma unroll
    for (int i = 0; i < 8; i++) {
        int row = bm + ((i < 4) ? (ty * 4 + i) : (64 + ty * 4 + (i - 4)));
        if (row >= M) continue;
        #pragma unroll
        for (int jj = 0; jj < 2; jj++) {
            int col = bn + jj * 64 + tx * 4;
            if (col >= N) continue;
            U64F2 p0, p1;
            p0.u = acc[i][jj * 2];
            p1.u = acc[i][jj * 2 + 1];
            float v0 = p0.f.x, v1 = p0.f.y, v2 = p1.f.x, v3 = p1.f.y;
            if (BIAS) {
                v0 += bias[col]; v1 += bias[col + 1];
                v2 += bias[col + 2]; v3 += bias[col + 3];
            }
            if (RELU) {
                v0 = fmaxf(v0, 0.f); v1 = fmaxf(v1, 0.f);
                v2 = fmaxf(v2, 0.f); v3 = fmaxf(v3, 0.f);
            }
            if (col + 3 < N) {
                *(float4*)(C + (size_t)row * ldc + col) = make_float4(v0, v1, v2, v3);
            } else {
                float vv[4] = {v0, v1, v2, v3};
                #pragma unroll
                for (int q = 0; q < 4; q++)
                    if (col + q < N) C[(size_t)row * ldc + col + q] = vv[q];
            }
        }
    }
}

// ---------------- final tiny MLP + softmax --------------------------------
__global__ void final_k(const float* __restrict__ Wg1, const float* __restrict__ bg1,
                        const float* __restrict__ Wg2, const float* __restrict__ bg2,
                        const float* __restrict__ Wg3, const float* __restrict__ bg3,
                        float* __restrict__ outv, float* __restrict__ outy) {
    __shared__ float vcat[2 * Hn];
    __shared__ float y1[Hn];
    __shared__ float y2[Hn];
    int t = threadIdx.x;  // 1024 threads
    vcat[t] = g_v[t];
    outv[t] = g_v[t];
    __syncthreads();
    if (t < Hn) {
        float s = bg1[t];
        for (int k = 0; k < 2 * Hn; k++) s += vcat[k] * Wg1[t * 2 * Hn + k];
        y1[t] = fmaxf(s, 0.f);
    }
    __syncthreads();
    if (t < Hn) {
        float s = bg2[t];
        for (int k = 0; k < Hn; k++) s += y1[k] * Wg2[t * Hn + k];
        y2[t] = fmaxf(s, 0.f);
    }
    __syncthreads();
    if (t == 0) {
        float z[3];
        float mx = -1e30f;
        for (int c = 0; c < 3; c++) {
            float s = bg3[c];
            for (int k = 0; k < Hn; k++) s += y2[k] * Wg3[c * Hn + k];
            z[c] = s;
            mx = fmaxf(mx, z[c]);
        }
        float se = 0.f;
        for (int c = 0; c < 3; c++) { z[c] = expf(z[c] - mx); se += z[c]; }
        for (int c = 0; c < 3; c++) outy[c] = z[c] / se;
    }
}

// ---------------- launch --------------------------------------------------
extern "C" void kernel_launch(void* const* d_in, const int* in_sizes, int n_in,
                              void* d_out, int out_size) {
    const int*   p_idx = (const int*)d_in[0];
    const int*   h_idx = (const int*)d_in[1];
    const float* emb   = (const float*)d_in[2];
    const float* W_a1  = (const float*)d_in[3];
    const float* b_a1  = (const float*)d_in[4];
    const float* W_a2  = (const float*)d_in[5];
    const float* b_a2  = (const float*)d_in[6];
    const float* W_c1  = (const float*)d_in[7];
    const float* b_c1  = (const float*)d_in[8];
    const float* W_c2  = (const float*)d_in[9];
    const float* b_c2  = (const float*)d_in[10];
    const float* W_g1  = (const float*)d_in[11];
    const float* b_g1  = (const float*)d_in[12];
    const float* W_g2  = (const float*)d_in[13];
    const float* b_g2  = (const float*)d_in[14];
    const float* W_g3  = (const float*)d_in[15];
    const float* b_g3  = (const float*)d_in[16];

    float* out      = (float*)d_out;
    float* outE     = out;                        // [4096,4096]
    float* outBeta  = outE + (size_t)LPn * LHn;   // [4096,300]
    float* outAlpha = outBeta + (size_t)LPn * Dn; // [4096,300]
    float* outV     = outAlpha + (size_t)LHn * Dn;// [1024] = v1|v2
    float* outY     = outV + 2 * Hn;              // [3]

    float *embp, *t1, *fa, *t2, *cat, *part, *eik, *ekj, *v;
    cudaGetSymbolAddress((void**)&embp, g_emb);
    cudaGetSymbolAddress((void**)&t1, g_t1);
    cudaGetSymbolAddress((void**)&fa, g_fa);
    cudaGetSymbolAddress((void**)&t2, g_t2);
    cudaGetSymbolAddress((void**)&cat, g_cat);
    cudaGetSymbolAddress((void**)&part, g_part);
    cudaGetSymbolAddress((void**)&eik, g_eik);
    cudaGetSymbolAddress((void**)&ekj, g_ekj);
    cudaGetSymbolAddress((void**)&v, g_v);

    const int TB = 256;
    const int MT = LPn + LHn;  // 8192 merged rows

    // gathers (p then h) + zero accumulators
    gather4_k<<<(LPn * (Dn / 4) + TB - 1) / TB, TB>>>(p_idx, emb, embp, LPn);
    gather4_k<<<(LHn * (Dn / 4) + TB - 1) / TB, TB>>>(h_idx, emb, embp + (size_t)LPn * Dn, LHn);
    zero_k<<<16, 256>>>();

    // attend (merged p|h): t1 = relu(emb@Wa1^T+b); fa = relu(t1@Wa2^T+b)
    sgemm128<false, true, true, true, false><<<dim3(Hn / 128, MT / 128), TB>>>(
        embp, Dn, W_a1, Dn, b_a1, t1, Hn, MT, Hn, Dn, 0);
    sgemm128<false, true, true, true, false><<<dim3(Hn / 128, MT / 128), TB>>>(
        t1, Hn, W_a2, Hn, b_a2, fa, Hn, MT, Hn, Hn, 0);

    // E = fp @ reshape(fh,[H,LH])  (plain NN GEMM on the fh buffer)
    sgemm128<false, false, false, false, false><<<dim3(LHn / 128, LPn / 128), TB>>>(
        fa, Hn, fa + (size_t)LPn * Hn, LHn, nullptr, outE, LHn, LPn, LHn, Hn, 0);

    // eik (row sums), ekj (col sums)
    rowsum_k<<<LPn / 8, 256>>>(outE, eik);
    colsum_acc_k<<<dim3(LHn / 256, 32), 256>>>(outE, ekj, LHn, LPn / 32);

    // beta partials: E @ hemb, split-K
    sgemm128<false, false, false, false, true>
        <<<dim3((Dn + 127) / 128, LPn / 128, NSPLIT), TB>>>(
        outE, LHn, embp + (size_t)LPn * Dn, Dn, nullptr, part, Dn,
        LPn, Dn, LHn, LHn / NSPLIT);
    reduce_scale_k<<<(LPn * Dn / 4 + TB - 1) / TB, TB>>>(part, eik, outBeta, LPn, Dn);

    // alpha partials: E^T @ pemb, split-K
    sgemm128<true, false, false, false, true>
        <<<dim3((Dn + 127) / 128, LHn / 128, NSPLIT), TB>>>(
        outE, LHn, embp, Dn, nullptr, part, Dn,
        LHn, Dn, LPn, LPn / NSPLIT);
    reduce_scale_k<<<(LHn * Dn / 4 + TB - 1) / TB, TB>>>(part, ekj, outAlpha, LHn, Dn);

    // comp (merged): cat -> two gemms -> column sums
    concat_k<<<(MT * (2 * Dn / 4) + TB - 1) / TB, TB>>>(outBeta, outAlpha, cat);
    sgemm128<false, true, true, true, false><<<dim3(Hn / 128, MT / 128), TB>>>(
        cat, 2 * Dn, W_c1, 2 * Dn, b_c1, t1, Hn, MT, Hn, 2 * Dn, 0);
    sgemm128<false, true, true, true, false><<<dim3(Hn / 128, MT / 128), TB>>>(
        t1, Hn, W_c2, Hn, b_c2, t2, Hn, MT, Hn, Hn, 0);
    colsum_acc_k<<<dim3(Hn / 256, 32), 256>>>(t2, v, Hn, LPn / 32);
    colsum_acc_k<<<dim3(Hn / 256, 32), 256>>>(t2 + (size_t)LPn * Hn, v + Hn, Hn, LHn / 32);

    // final head: writes v1|v2 and softmax y
    final_k<<<1, 1024>>>(W_g1, b_g1, W_g2, b_g2, W_g3, b_g3, outV, outY);
}

// round 4
// speedup vs baseline: 1.6513x; 1.0268x over previous
#include <cuda_runtime.h>
#include <cstdint>

#define LPn 4096
#define LHn 4096
#define Dn 300
#define Hn 512
#define SAW 136                     // smem row stride (words), conflict-free
#define STAGE_WORDS (2 * 32 * SAW)  // A tile + B tile per stage
#define SMEM_BYTES (2 * STAGE_WORDS * 4)

// ---------------- scratch (device globals; no allocation allowed) ----------
__device__ float g_emb[(LPn + LHn) * Dn];  // p rows then h rows
__device__ float g_t1[(LPn + LHn) * Hn];
__device__ float g_fa[(LPn + LHn) * Hn];   // attend out: fp | fh
__device__ float g_t2[(LPn + LHn) * Hn];
__device__ float g_cat[(LPn + LHn) * 2 * Dn];
__device__ float g_eik[LPn];
__device__ float g_ekj[LHn];
__device__ float g_v[2 * Hn];

// ---------------- helpers ---------------------------------------------------
__device__ __forceinline__ uint32_t f2tf(float x) {
    uint32_t u;
    asm("cvt.rna.tf32.f32 %0, %1;" : "=r"(u) : "f"(x));
    return u;
}

__device__ __forceinline__ void mma8(float* c, const uint32_t* a, uint32_t b0, uint32_t b1) {
    asm volatile(
        "mma.sync.aligned.m16n8k8.row.col.f32.tf32.tf32.f32 "
        "{%0,%1,%2,%3}, {%4,%5,%6,%7}, {%8,%9}, {%0,%1,%2,%3};"
        : "+f"(c[0]), "+f"(c[1]), "+f"(c[2]), "+f"(c[3])
        : "r"(a[0]), "r"(a[1]), "r"(a[2]), "r"(a[3]), "r"(b0), "r"(b1));
}

// ---------------- tile loaders ---------------------------------------------
// direct: src row-major [rows, ld]; tile[r][k] = src[row0+r][k0+k]; dst layout [k][r]
__device__ __forceinline__ void loadDirect(const float* __restrict__ src, int ld,
                                           int row0, int rlim, int k0, int K, float4 r[4]) {
    int t = threadIdx.x;
    int rr = t >> 1, hk = (t & 1) * 16;
    int gr = row0 + rr;
    bool rok = gr < rlim;
    const float* p = src + (size_t)gr * ld + k0 + hk;
#pragma unroll
    for (int j = 0; j < 4; j++) {
        int kk = k0 + hk + j * 4;
        float4 v = make_float4(0.f, 0.f, 0.f, 0.f);
        if (rok) {
            if (kk + 3 < K) {
                v = *(const float4*)(p + j * 4);
            } else if (kk < K) {
                float tmp[4] = {0.f, 0.f, 0.f, 0.f};
#pragma unroll
                for (int q = 0; q < 4; q++)
                    if (kk + q < K) tmp[q] = p[j * 4 + q];
                v = make_float4(tmp[0], tmp[1], tmp[2], tmp[3]);
            }
        }
        r[j] = v;
    }
}
__device__ __forceinline__ void stsDirect(const float4 r[4], uint32_t* __restrict__ sdst) {
    int t = threadIdx.x;
    int rr = t >> 1, hk = (t & 1) * 16;
#pragma unroll
    for (int j = 0; j < 4; j++) {
        int k = hk + j * 4;
        sdst[(k + 0) * SAW + rr] = f2tf(r[j].x);
        sdst[(k + 1) * SAW + rr] = f2tf(r[j].y);
        sdst[(k + 2) * SAW + rr] = f2tf(r[j].z);
        sdst[(k + 3) * SAW + rr] = f2tf(r[j].w);
    }
}

// trans: src row-major [Ktot, ld]; tile[c][k] = src[k0+k][c0+c]; dst layout [k][c]
__device__ __forceinline__ void loadTrans(const float* __restrict__ src, int ld,
                                          int c0, int clim, int k0, int Ktot, float4 r[4]) {
    int t = threadIdx.x;
    int k = t >> 3, c4 = (t & 7) * 16;
    bool kok = (k0 + k) < Ktot;
    const float* p = src + (size_t)(k0 + k) * ld + c0 + c4;
#pragma unroll
    for (int j = 0; j < 4; j++) {
        int gc = c0 + c4 + j * 4;
        float4 v = make_float4(0.f, 0.f, 0.f, 0.f);
        if (kok) {
            if (gc + 3 < clim) {
                v = *(const float4*)(p + j * 4);
            } else if (gc < clim) {
                float tmp[4] = {0.f, 0.f, 0.f, 0.f};
#pragma unroll
                for (int q = 0; q < 4; q++)
                    if (gc + q < clim) tmp[q] = p[j * 4 + q];
                v = make_float4(tmp[0], tmp[1], tmp[2], tmp[3]);
            }
        }
        r[j] = v;
    }
}
__device__ __forceinline__ void stsTrans(const float4 r[4], uint32_t* __restrict__ sdst) {
    int t = threadIdx.x;
    int k = t >> 3, c4 = (t & 7) * 16;
#pragma unroll
    for (int j = 0; j < 4; j++) {
        uint4 u = make_uint4(f2tf(r[j].x), f2tf(r[j].y), f2tf(r[j].z), f2tf(r[j].w));
        *(uint4*)&sdst[k * SAW + c4 + j * 4] = u;
    }
}

// ---------------- mma.sync tf32 GEMM ---------------------------------------
// C[M,N] = A @ B.
//   AT=0: A src row-major [M,K]. AT=1: A[m,k] = src[k*lda + m] (src [K, lda]).
//   BT=0: B src = W [N,K] row-major (B[k,n]=W[n][k]). BT=1: B src [K,N] row-major.
// EPI: 0 none; 1 bias+relu (aux=bias[N]); 2 row scale by 1/aux[row].
template <bool AT, bool BT, int EPI>
__global__ void __launch_bounds__(256)
tgemm(const float* __restrict__ A, int lda,
      const float* __restrict__ B, int ldb,
      const float* __restrict__ aux,
      float* __restrict__ C, int ldc,
      int M, int N, int K) {
    extern __shared__ uint32_t sm[];
    const int tid = threadIdx.x, wid = tid >> 5, lane = tid & 31;
    const int gid = lane >> 2, tig = lane & 3;
    const int wm = wid >> 1, wn = wid & 1;
    const int bm = blockIdx.y * 128, bn = blockIdx.x * 128;

    float acc[2][8][4];
#pragma unroll
    for (int i = 0; i < 2; i++)
#pragma unroll
        for (int j = 0; j < 8; j++)
#pragma unroll
            for (int q = 0; q < 4; q++) acc[i][j][q] = 0.f;

    const int NC = (K + 31) / 32;
    float4 ra[4], rb[4];

    // prologue: chunk 0 -> stage 0
    if (AT) loadTrans(A, lda, bm, M, 0, K, ra);
    else    loadDirect(A, lda, bm, M, 0, K, ra);
    if (BT) loadTrans(B, ldb, bn, N, 0, K, rb);
    else    loadDirect(B, ldb, bn, N, 0, K, rb);
    if (AT) stsTrans(ra, sm);
    else    stsDirect(ra, sm);
    if (BT) stsTrans(rb, sm + 32 * SAW);
    else    stsDirect(rb, sm + 32 * SAW);
    __syncthreads();

    for (int kc = 0; kc < NC; kc++) {
        int s = kc & 1;
        if (kc + 1 < NC) {
            int k0 = (kc + 1) * 32;
            if (AT) loadTrans(A, lda, bm, M, k0, K, ra);
            else    loadDirect(A, lda, bm, M, k0, K, ra);
            if (BT) loadTrans(B, ldb, bn, N, k0, K, rb);
            else    loadDirect(B, ldb, bn, N, k0, K, rb);
        }
        const uint32_t* SA_p = sm + s * STAGE_WORDS;
        const uint32_t* SB_p = SA_p + 32 * SAW;
#pragma unroll
        for (int kk = 0; kk < 4; kk++) {
            int k8 = kk * 8;
            uint32_t a[2][4];
#pragma unroll
            for (int mi = 0; mi < 2; mi++) {
                int m0 = wm * 32 + mi * 16;
                a[mi][0] = SA_p[(k8 + tig) * SAW + m0 + gid];
                a[mi][1] = SA_p[(k8 + tig) * SAW + m0 + gid + 8];
                a[mi][2] = SA_p[(k8 + tig + 4) * SAW + m0 + gid];
                a[mi][3] = SA_p[(k8 + tig + 4) * SAW + m0 + gid + 8];
            }
#pragma unroll
            for (int ni = 0; ni < 8; ni++) {
                int n0 = wn * 64 + ni * 8;
                uint32_t b0 = SB_p[(k8 + tig) * SAW + n0 + gid];
                uint32_t b1 = SB_p[(k8 + tig + 4) * SAW + n0 + gid];
                mma8(acc[0][ni], a[0], b0, b1);
                mma8(acc[1][ni], a[1], b0, b1);
            }
        }
        if (kc + 1 < NC) {
            uint32_t* dA = sm + (s ^ 1) * STAGE_WORDS;
            if (AT) stsTrans(ra, dA);
            else    stsDirect(ra, dA);
            if (BT) stsTrans(rb, dA + 32 * SAW);
            else    stsDirect(rb, dA + 32 * SAW);
        }
        __syncthreads();
    }

    // epilogue
    float rs[2][2];
    if (EPI == 2) {
#pragma unroll
        for (int mi = 0; mi < 2; mi++) {
            int r0 = bm + wm * 32 + mi * 16 + gid;
            rs[mi][0] = 1.f / aux[r0];
            rs[mi][1] = 1.f / aux[r0 + 8];
        }
    }
#pragma unroll
    for (int mi = 0; mi < 2; mi++) {
#pragma unroll
        for (int ni = 0; ni < 8; ni++) {
            int col = bn + wn * 64 + ni * 8 + tig * 2;
            if (col >= N) continue;
            int r0 = bm + wm * 32 + mi * 16 + gid;
            float v0 = acc[mi][ni][0], v1 = acc[mi][ni][1];
            float v2 = acc[mi][ni][2], v3 = acc[mi][ni][3];
            if (EPI == 1) {
                float bi0 = aux[col];
                float bi1 = (col + 1 < N) ? aux[col + 1] : 0.f;
                v0 = fmaxf(v0 + bi0, 0.f); v1 = fmaxf(v1 + bi1, 0.f);
                v2 = fmaxf(v2 + bi0, 0.f); v3 = fmaxf(v3 + bi1, 0.f);
            }
            if (EPI == 2) {
                v0 *= rs[mi][0]; v1 *= rs[mi][0];
                v2 *= rs[mi][1]; v3 *= rs[mi][1];
            }
            float* c0p = C + (size_t)r0 * ldc + col;
            float* c1p = C + (size_t)(r0 + 8) * ldc + col;
            if (col + 1 < N) {
                *(float2*)c0p = make_float2(v0, v1);
                *(float2*)c1p = make_float2(v2, v3);
            } else {
                *c0p = v0;
                *c1p = v2;
            }
        }
    }
}

// ---------------- small kernels -------------------------------------------
__global__ void gather4_k(const int* __restrict__ idx, const float* __restrict__ emb,
                          float* __restrict__ dst, int rows) {
    int t = blockIdx.x * blockDim.x + threadIdx.x;
    if (t < rows * (Dn / 4)) {
        int r = t / (Dn / 4), c = t - r * (Dn / 4);
        ((float4*)dst)[t] = ((const float4*)(emb + (size_t)idx[r] * Dn))[c];
    }
}

__global__ void zero_k() {
    int t = blockIdx.x * blockDim.x + threadIdx.x;
    if (t < LHn) g_ekj[t] = 0.f;
    if (t < 2 * Hn) g_v[t] = 0.f;
}

__global__ void rowsum_k(const float* __restrict__ E, float* __restrict__ out) {
    int row = blockIdx.x * (blockDim.x / 32) + (threadIdx.x >> 5);
    int lane = threadIdx.x & 31;
    const float4* p = (const float4*)(E + (size_t)row * LHn);
    float s = 0.f;
    for (int j = lane; j < LHn / 4; j += 32) {
        float4 v = p[j];
        s += (v.x + v.y) + (v.z + v.w);
    }
#pragma unroll
    for (int o = 16; o; o >>= 1) s += __shfl_xor_sync(0xffffffffu, s, o);
    if (lane == 0) out[row] = s;
}

__global__ void colsum_acc_k(const float* __restrict__ X, float* __restrict__ out,
                             int cols, int rows_per_blk) {
    int col = blockIdx.x * blockDim.x + threadIdx.x;
    if (col >= cols) return;
    long r0 = (long)blockIdx.y * rows_per_blk;
    float s = 0.f;
    for (long r = r0; r < r0 + rows_per_blk; r++) s += X[r * cols + col];
    atomicAdd(&out[col], s);
}

__global__ void concat_k(const float* __restrict__ beta, const float* __restrict__ alpha,
                         float* __restrict__ dst) {
    int t = blockIdx.x * blockDim.x + threadIdx.x;
    if (t >= (LPn + LHn) * (2 * Dn / 4)) return;
    int R = t / (2 * Dn / 4), c4 = t - R * (2 * Dn / 4);
    float4 v;
    if (c4 < Dn / 4) {
        v = ((const float4*)(g_emb + (size_t)R * Dn))[c4];
    } else {
        const float* src = (R < LPn) ? (beta + (size_t)R * Dn)
                                     : (alpha + (size_t)(R - LPn) * Dn);
        v = ((const float4*)src)[c4 - Dn / 4];
    }
    ((float4*)dst)[t] = v;
}

__global__ void final_k(const float* __restrict__ Wg1, const float* __restrict__ bg1,
                        const float* __restrict__ Wg2, const float* __restrict__ bg2,
                        const float* __restrict__ Wg3, const float* __restrict__ bg3,
                        float* __restrict__ outv, float* __restrict__ outy) {
    __shared__ float vcat[2 * Hn];
    __shared__ float y1[Hn];
    __shared__ float y2[Hn];
    int t = threadIdx.x;  // 1024
    vcat[t] = g_v[t];
    outv[t] = g_v[t];
    __syncthreads();
    if (t < Hn) {
        float s = bg1[t];
        for (int k = 0; k < 2 * Hn; k++) s += vcat[k] * Wg1[t * 2 * Hn + k];
        y1[t] = fmaxf(s, 0.f);
    }
    __syncthreads();
    if (t < Hn) {
        float s = bg2[t];
        for (int k = 0; k < Hn; k++) s += y1[k] * Wg2[t * Hn + k];
        y2[t] = fmaxf(s, 0.f);
    }
    __syncthreads();
    if (t == 0) {
        float z[3];
        float mx = -1e30f;
        for (int c = 0; c < 3; c++) {
            float s = bg3[c];
            for (int k = 0; k < Hn; k++) s += y2[k] * Wg3[c * Hn + k];
            z[c] = s;
            mx = fmaxf(mx, z[c]);
        }
        float se = 0.f;
        for (int c = 0; c < 3; c++) { z[c] = expf(z[c] - mx); se += z[c]; }
        for (int c = 0; c < 3; c++) outy[c] = z[c] / se;
    }
}

// ---------------- launch --------------------------------------------------
extern "C" void kernel_launch(void* const* d_in, const int* in_sizes, int n_in,
                              void* d_out, int out_size) {
    const int*   p_idx = (const int*)d_in[0];
    const int*   h_idx = (const int*)d_in[1];
    const float* emb   = (const float*)d_in[2];
    const float* W_a1  = (const float*)d_in[3];
    const float* b_a1  = (const float*)d_in[4];
    const float* W_a2  = (const float*)d_in[5];
    const float* b_a2  = (const float*)d_in[6];
    const float* W_c1  = (const float*)d_in[7];
    const float* b_c1  = (const float*)d_in[8];
    const float* W_c2  = (const float*)d_in[9];
    const float* b_c2  = (const float*)d_in[10];
    const float* W_g1  = (const float*)d_in[11];
    const float* b_g1  = (const float*)d_in[12];
    const float* W_g2  = (const float*)d_in[13];
    const float* b_g2  = (const float*)d_in[14];
    const float* W_g3  = (const float*)d_in[15];
    const float* b_g3  = (const float*)d_in[16];

    float* out      = (float*)d_out;
    float* outE     = out;
    float* outBeta  = outE + (size_t)LPn * LHn;
    float* outAlpha = outBeta + (size_t)LPn * Dn;
    float* outV     = outAlpha + (size_t)LHn * Dn;
    float* outY     = outV + 2 * Hn;

    float *embp, *t1, *fa, *t2, *cat, *eik, *ekj, *v;
    cudaGetSymbolAddress((void**)&embp, g_emb);
    cudaGetSymbolAddress((void**)&t1, g_t1);
    cudaGetSymbolAddress((void**)&fa, g_fa);
    cudaGetSymbolAddress((void**)&t2, g_t2);
    cudaGetSymbolAddress((void**)&cat, g_cat);
    cudaGetSymbolAddress((void**)&eik, g_eik);
    cudaGetSymbolAddress((void**)&ekj, g_ekj);
    cudaGetSymbolAddress((void**)&v, g_v);

    cudaFuncSetAttribute(tgemm<false, false, 1>, cudaFuncAttributeMaxDynamicSharedMemorySize, SMEM_BYTES);
    cudaFuncSetAttribute(tgemm<false, true, 0>,  cudaFuncAttributeMaxDynamicSharedMemorySize, SMEM_BYTES);
    cudaFuncSetAttribute(tgemm<false, true, 2>,  cudaFuncAttributeMaxDynamicSharedMemorySize, SMEM_BYTES);
    cudaFuncSetAttribute(tgemm<true, true, 2>,   cudaFuncAttributeMaxDynamicSharedMemorySize, SMEM_BYTES);

    const int TB = 256;
    const int MT = LPn + LHn;  // 8192

    gather4_k<<<(LPn * (Dn / 4) + TB - 1) / TB, TB>>>(p_idx, emb, embp, LPn);
    gather4_k<<<(LHn * (Dn / 4) + TB - 1) / TB, TB>>>(h_idx, emb, embp + (size_t)LPn * Dn, LHn);
    zero_k<<<16, 256>>>();

    // attend (merged p|h): t1 = relu(emb@Wa1^T+b); fa = relu(t1@Wa2^T+b)
    tgemm<false, false, 1><<<dim3(Hn / 128, MT / 128), 256, SMEM_BYTES>>>(
        embp, Dn, W_a1, Dn, b_a1, t1, Hn, MT, Hn, Dn);
    tgemm<false, false, 1><<<dim3(Hn / 128, MT / 128), 256, SMEM_BYTES>>>(
        t1, Hn, W_a2, Hn, b_a2, fa, Hn, MT, Hn, Hn);

    // E = fp @ reshape(fh,[H,LH]) : B src [K=512, N=4096] row-major
    tgemm<false, true, 0><<<dim3(LHn / 128, LPn / 128), 256, SMEM_BYTES>>>(
        fa, Hn, fa + (size_t)LPn * Hn, LHn, nullptr, outE, LHn, LPn, LHn, Hn);

    rowsum_k<<<LPn / 8, 256>>>(outE, eik);
    colsum_acc_k<<<dim3(LHn / 256, 32), 256>>>(outE, ekj, LHn, LPn / 32);

    // beta = (E/eik) @ hemb : A=E direct, B src [K=4096, N=300]
    tgemm<false, true, 2><<<dim3((Dn + 127) / 128, LPn / 128), 256, SMEM_BYTES>>>(
        outE, LHn, embp + (size_t)LPn * Dn, Dn, eik, outBeta, Dn, LPn, Dn, LHn);

    // alpha = (E/ekj)^T @ pemb : A trans src E, B src [K=4096, N=300]
    tgemm<true, true, 2><<<dim3((Dn + 127) / 128, LHn / 128), 256, SMEM_BYTES>>>(
        outE, LHn, embp, Dn, ekj, outAlpha, Dn, LHn, Dn, LPn);

    // comp (merged)
    concat_k<<<(MT * (2 * Dn / 4) + TB - 1) / TB, TB>>>(outBeta, outAlpha, cat);
    tgemm<false, false, 1><<<dim3(Hn / 128, MT / 128), 256, SMEM_BYTES>>>(
        cat, 2 * Dn, W_c1, 2 * Dn, b_c1, t1, Hn, MT, Hn, 2 * Dn);
    tgemm<false, false, 1><<<dim3(Hn / 128, MT / 128), 256, SMEM_BYTES>>>(
        t1, Hn, W_c2, Hn, b_c2, t2, Hn, MT, Hn, Hn);
    colsum_acc_k<<<dim3(Hn / 256, 32), 256>>>(t2, v, Hn, LPn / 32);
    colsum_acc_k<<<dim3(Hn / 256, 32), 256>>>(t2 + (size_t)LPn * Hn, v + Hn, Hn, LHn / 32);

    final_k<<<1, 1024>>>(W_g1, b_g1, W_g2, b_g2, W_g3, b_g3, outV, outY);
}

// round 5
// speedup vs baseline: 3.4524x; 2.0907x over previous
#include <cuda_runtime.h>
#include <cstdint>

#define LPn 4096
#define LHn 4096
#define Dn 300
#define Hn 512
#define NSPLIT 4

// ---------------- scratch (device globals; no allocation allowed) ----------
__device__ float g_emb[(LPn + LHn) * Dn];  // p rows then h rows (tf32-rounded)
__device__ float g_t1[(LPn + LHn) * Hn];
__device__ float g_fa[(LPn + LHn) * Hn];   // attend out: fp | fh (rounded)
__device__ float g_t2[(LPn + LHn) * Hn];
__device__ float g_cat[(LPn + LHn) * 2 * Dn];
__device__ float g_part[NSPLIT * LPn * Dn];
__device__ float g_eik[LPn];
__device__ float g_ekj[LHn];
__device__ float g_v[2 * Hn];
__device__ float g_wa1[Hn * Dn];
__device__ float g_wa2[Hn * Hn];
__device__ float g_wc1[Hn * 2 * Dn];
__device__ float g_wc2[Hn * Hn];

// ---------------- helpers ---------------------------------------------------
__device__ __forceinline__ uint32_t f2tf(float x) {
    uint32_t u;
    asm("cvt.rna.tf32.f32 %0, %1;" : "=r"(u) : "f"(x));
    return u;
}
__device__ __forceinline__ float roundtf(float x) { return __uint_as_float(f2tf(x)); }

__device__ __forceinline__ void cpa16(uint32_t saddr, const float* g, uint32_t vb) {
    asm volatile("cp.async.cg.shared.global [%0], [%1], 16, %2;"
                 ::"r"(saddr), "l"(g), "r"(vb));
}
#define CP_COMMIT() asm volatile("cp.async.commit_group;" ::: "memory")
#define CP_WAIT1() asm volatile("cp.async.wait_group 1;" ::: "memory")

__device__ __forceinline__ void mma8(float* c, const uint32_t* a, uint32_t b0, uint32_t b1) {
    asm volatile(
        "mma.sync.aligned.m16n8k8.row.col.f32.tf32.tf32.f32 "
        "{%0,%1,%2,%3}, {%4,%5,%6,%7}, {%8,%9}, {%0,%1,%2,%3};"
        : "+f"(c[0]), "+f"(c[1]), "+f"(c[2]), "+f"(c[3])
        : "r"(a[0]), "r"(a[1]), "r"(a[2]), "r"(a[3]), "r"(b0), "r"(b1));
}

// direct: src row-major [rows, ld]; chunk cols [k0,k0+32) -> smem [r][k] stride 36
__device__ __forceinline__ void loadDirectAsync(const float* __restrict__ src, int ld,
                                                int row0, int rlim, int k0, int kend,
                                                uint32_t saddr) {
    int t = threadIdx.x;
    int r = t >> 1, half = (t & 1) * 16;
    int gr = row0 + r;
    bool rok = gr < rlim;
    const float* p = src + (size_t)(rok ? gr : row0) * ld + k0 + half;
    uint32_t sa = saddr + (uint32_t)(r * 36 + half) * 4;
#pragma unroll
    for (int j = 0; j < 4; j++) {
        int gk = k0 + half + j * 4;
        uint32_t vb = (rok && gk + 3 < kend) ? 16u : 0u;
        cpa16(sa + j * 16, p + j * 4, vb);
    }
}

// trans: src row-major [Ktot, ld]; rows [k0,k0+32), cols [c0,c0+128) -> smem [k][c] stride 136
__device__ __forceinline__ void loadTransAsync(const float* __restrict__ src, int ld,
                                               int c0, int clim, int k0, int kend,
                                               uint32_t saddr) {
    int t = threadIdx.x;
    int k = t >> 3;
    int gk = k0 + k;
    bool kok = gk < kend;
    const float* p = src + (size_t)(kok ? gk : k0) * ld + c0;
    uint32_t sa = saddr + (uint32_t)(k * 136) * 4;
#pragma unroll
    for (int j = 0; j < 4; j++) {
        int c = ((t & 7) + j * 8) * 4;
        uint32_t vb = (kok && c0 + c + 3 < clim) ? 16u : 0u;
        cpa16(sa + (uint32_t)c * 4, p + c, vb);
    }
}

// ---------------- mma.sync tf32 GEMM, cp.async 3-stage ---------------------
// C[M,N] = A @ B.
//   AT=0: A row-major [M,K]. AT=1: A[m,k]=src[k*lda+m] (src [K,lda]).
//   BT=0: B = W [N,K] row-major. BT=1: B src [K,N] row-major.
// EPI: 0 none; 1 bias+relu (aux=bias[N]).  ROUND: tf32-round stores.
// SPLITK: blockIdx.z picks K range, C += z*M*ldc (partials).
template <bool AT, bool BT, int EPI, bool ROUND, bool SPLITK>
__global__ void __launch_bounds__(256, 2)
tgemm(const float* __restrict__ A, int lda,
      const float* __restrict__ B, int ldb,
      const float* __restrict__ aux,
      float* __restrict__ C, int ldc,
      int M, int N, int K, int Ksub) {
    constexpr int AW = AT ? 32 * 136 : 128 * 36;
    constexpr int BW = BT ? 32 * 136 : 128 * 36;
    constexpr int STW = AW + BW;
    extern __shared__ uint32_t sm[];
    const uint32_t sbase = (uint32_t)__cvta_generic_to_shared(sm);

    const int tid = threadIdx.x, wid = tid >> 5, lane = tid & 31;
    const int gid = lane >> 2, tig = lane & 3;
    const int wm = wid >> 1, wn = wid & 1;
    const int bm = blockIdx.y * 128, bn = blockIdx.x * 128;

    int k_off = 0, Kloc = K;
    if (SPLITK) {
        k_off = blockIdx.z * Ksub;
        Kloc = Ksub;
        C += (size_t)blockIdx.z * M * ldc;
    }
    const int kend = k_off + Kloc;
    const int NC = (Kloc + 31) / 32;

    float acc[2][8][4];
#pragma unroll
    for (int i = 0; i < 2; i++)
#pragma unroll
        for (int j = 0; j < 8; j++)
#pragma unroll
            for (int q = 0; q < 4; q++) acc[i][j][q] = 0.f;

    // prologue: chunks 0,1 -> stages 0,1
#pragma unroll
    for (int pc = 0; pc < 2; pc++) {
        uint32_t sA = sbase + (uint32_t)(pc * STW) * 4;
        uint32_t sB = sA + (uint32_t)AW * 4;
        int k0 = k_off + pc * 32;
        if (AT) loadTransAsync(A, lda, bm, M, k0, kend, sA);
        else    loadDirectAsync(A, lda, bm, M, k0, kend, sA);
        if (BT) loadTransAsync(B, ldb, bn, N, k0, kend, sB);
        else    loadDirectAsync(B, ldb, bn, N, k0, kend, sB);
        CP_COMMIT();
    }

    for (int kc = 0; kc < NC; kc++) {
        CP_WAIT1();
        __syncthreads();
        if (kc + 2 < NC) {
            int st = (kc + 2) % 3;
            int k0 = k_off + (kc + 2) * 32;
            uint32_t sA = sbase + (uint32_t)(st * STW) * 4;
            uint32_t sB = sA + (uint32_t)AW * 4;
            if (AT) loadTransAsync(A, lda, bm, M, k0, kend, sA);
            else    loadDirectAsync(A, lda, bm, M, k0, kend, sA);
            if (BT) loadTransAsync(B, ldb, bn, N, k0, kend, sB);
            else    loadDirectAsync(B, ldb, bn, N, k0, kend, sB);
        }
        CP_COMMIT();

        const uint32_t* SA_p = sm + (kc % 3) * STW;
        const uint32_t* SB_p = SA_p + AW;
#pragma unroll
        for (int kk = 0; kk < 4; kk++) {
            int k8 = kk * 8;
            uint32_t a[2][4];
#pragma unroll
            for (int mi = 0; mi < 2; mi++) {
                int m0 = wm * 32 + mi * 16;
                if (AT) {
                    a[mi][0] = SA_p[(k8 + tig) * 136 + m0 + gid];
                    a[mi][1] = SA_p[(k8 + tig) * 136 + m0 + gid + 8];
                    a[mi][2] = SA_p[(k8 + tig + 4) * 136 + m0 + gid];
                    a[mi][3] = SA_p[(k8 + tig + 4) * 136 + m0 + gid + 8];
                } else {
                    a[mi][0] = SA_p[(m0 + gid) * 36 + k8 + tig];
                    a[mi][1] = SA_p[(m0 + gid + 8) * 36 + k8 + tig];
                    a[mi][2] = SA_p[(m0 + gid) * 36 + k8 + tig + 4];
                    a[mi][3] = SA_p[(m0 + gid + 8) * 36 + k8 + tig + 4];
                }
            }
#pragma unroll
            for (int ni = 0; ni < 8; ni++) {
                int n0 = wn * 64 + ni * 8;
                uint32_t b0, b1;
                if (BT) {
                    b0 = SB_p[(k8 + tig) * 136 + n0 + gid];
                    b1 = SB_p[(k8 + tig + 4) * 136 + n0 + gid];
                } else {
                    b0 = SB_p[(n0 + gid) * 36 + k8 + tig];
                    b1 = SB_p[(n0 + gid) * 36 + k8 + tig + 4];
                }
                mma8(acc[0][ni], a[0], b0, b1);
                mma8(acc[1][ni], a[1], b0, b1);
            }
        }
    }

    // epilogue
#pragma unroll
    for (int mi = 0; mi < 2; mi++) {
#pragma unroll
        for (int ni = 0; ni < 8; ni++) {
            int col = bn + wn * 64 + ni * 8 + tig * 2;
            if (col >= N) continue;
            int r0 = bm + wm * 32 + mi * 16 + gid;
            float v0 = acc[mi][ni][0], v1 = acc[mi][ni][1];
            float v2 = acc[mi][ni][2], v3 = acc[mi][ni][3];
            if (EPI == 1) {
                float bi0 = aux[col];
                float bi1 = (col + 1 < N) ? aux[col + 1] : 0.f;
                v0 = fmaxf(v0 + bi0, 0.f); v1 = fmaxf(v1 + bi1, 0.f);
                v2 = fmaxf(v2 + bi0, 0.f); v3 = fmaxf(v3 + bi1, 0.f);
            }
            if (ROUND) {
                v0 = roundtf(v0); v1 = roundtf(v1);
                v2 = roundtf(v2); v3 = roundtf(v3);
            }
            float* c0p = C + (size_t)r0 * ldc + col;
            float* c1p = C + (size_t)(r0 + 8) * ldc + col;
            if (col + 1 < N) {
                *(float2*)c0p = make_float2(v0, v1);
                *(float2*)c1p = make_float2(v2, v3);
            } else {
                *c0p = v0;
                *c1p = v2;
            }
        }
    }
}

// ---------------- small kernels -------------------------------------------
__global__ void gather4_k(const int* __restrict__ idx, const float* __restrict__ emb,
                          float* __restrict__ dst, int rows) {
    int t = blockIdx.x * blockDim.x + threadIdx.x;
    if (t < rows * (Dn / 4)) {
        int r = t / (Dn / 4), c = t - r * (Dn / 4);
        float4 v = ((const float4*)(emb + (size_t)idx[r] * Dn))[c];
        v.x = roundtf(v.x); v.y = roundtf(v.y);
        v.z = roundtf(v.z); v.w = roundtf(v.w);
        ((float4*)dst)[t] = v;
    }
}

__global__ void cvtw_k(const float* __restrict__ w, float* __restrict__ dst, int n) {
    int t = blockIdx.x * blockDim.x + threadIdx.x;
    if (t < n) dst[t] = roundtf(w[t]);
}

__global__ void zero_k() {
    int t = blockIdx.x * blockDim.x + threadIdx.x;
    if (t < LHn) g_ekj[t] = 0.f;
    if (t < 2 * Hn) g_v[t] = 0.f;
}

__global__ void rowsum_k(const float* __restrict__ E, float* __restrict__ out) {
    int row = blockIdx.x * (blockDim.x / 32) + (threadIdx.x >> 5);
    int lane = threadIdx.x & 31;
    const float4* p = (const float4*)(E + (size_t)row * LHn);
    float s = 0.f;
    for (int j = lane; j < LHn / 4; j += 32) {
        float4 v = p[j];
        s += (v.x + v.y) + (v.z + v.w);
    }
#pragma unroll
    for (int o = 16; o; o >>= 1) s += __shfl_xor_sync(0xffffffffu, s, o);
    if (lane == 0) out[row] = s;
}

__global__ void colsum_acc_k(const float* __restrict__ X, float* __restrict__ out,
                             int cols, int rows_per_blk) {
    int col = blockIdx.x * blockDim.x + threadIdx.x;
    if (col >= cols) return;
    long r0 = (long)blockIdx.y * rows_per_blk;
    float s = 0.f;
    for (long r = r0; r < r0 + rows_per_blk; r++) s += X[r * cols + col];
    atomicAdd(&out[col], s);
}

__global__ void concat_k(const float* __restrict__ beta, const float* __restrict__ alpha,
                         float* __restrict__ dst) {
    int t = blockIdx.x * blockDim.x + threadIdx.x;
    if (t >= (LPn + LHn) * (2 * Dn / 4)) return;
    int R = t / (2 * Dn / 4), c4 = t - R * (2 * Dn / 4);
    float4 v;
    if (c4 < Dn / 4) {
        v = ((const float4*)(g_emb + (size_t)R * Dn))[c4];  // already rounded
    } else {
        const float* src = (R < LPn) ? (beta + (size_t)R * Dn)
                                     : (alpha + (size_t)(R - LPn) * Dn);
        v = ((const float4*)src)[c4 - Dn / 4];
        v.x = roundtf(v.x); v.y = roundtf(v.y);
        v.z = roundtf(v.z); v.w = roundtf(v.w);
    }
    ((float4*)dst)[t] = v;
}

// sum NSPLIT partials, scale rows by 1/scale[row]
__global__ void reduce_scale_k(const float* __restrict__ part,
                               const float* __restrict__ scale,
                               float* __restrict__ out, int M, int N) {
    int t = blockIdx.x * blockDim.x + threadIdx.x;
    if (t >= M * N / 4) return;
    float4 s = make_float4(0.f, 0.f, 0.f, 0.f);
#pragma unroll
    for (int z = 0; z < NSPLIT; z++) {
        float4 v = ((const float4*)(part + (size_t)z * M * N))[t];
        s.x += v.x; s.y += v.y; s.z += v.z; s.w += v.w;
    }
    int row = (t * 4) / N;
    float r = 1.f / scale[row];
    s.x *= r; s.y *= r; s.z *= r; s.w *= r;
    ((float4*)out)[t] = s;
}

__global__ void final_k(const float* __restrict__ Wg1, const float* __restrict__ bg1,
                        const float* __restrict__ Wg2, const float* __restrict__ bg2,
                        const float* __restrict__ Wg3, const float* __restrict__ bg3,
                        float* __restrict__ outv, float* __restrict__ outy) {
    __shared__ float vcat[2 * Hn];
    __shared__ float y1[Hn];
    __shared__ float y2[Hn];
    int t = threadIdx.x;  // 1024
    vcat[t] = g_v[t];
    outv[t] = g_v[t];
    __syncthreads();
    if (t < Hn) {
        float s = bg1[t];
        for (int k = 0; k < 2 * Hn; k++) s += vcat[k] * Wg1[t * 2 * Hn + k];
        y1[t] = fmaxf(s, 0.f);
    }
    __syncthreads();
    if (t < Hn) {
        float s = bg2[t];
        for (int k = 0; k < Hn; k++) s += y1[k] * Wg2[t * Hn + k];
        y2[t] = fmaxf(s, 0.f);
    }
    __syncthreads();
    if (t == 0) {
        float z[3];
        float mx = -1e30f;
        for (int c = 0; c < 3; c++) {
            float s = bg3[c];
            for (int k = 0; k < Hn; k++) s += y2[k] * Wg3[c * Hn + k];
            z[c] = s;
            mx = fmaxf(mx, z[c]);
        }
        float se = 0.f;
        for (int c = 0; c < 3; c++) { z[c] = expf(z[c] - mx); se += z[c]; }
        for (int c = 0; c < 3; c++) outy[c] = z[c] / se;
    }
}

// ---------------- launch --------------------------------------------------
static int smem_bytes(bool at, bool bt) {
    int aw = at ? 32 * 136 : 128 * 36;
    int bw = bt ? 32 * 136 : 128 * 36;
    return 3 * (aw + bw) * 4;
}

extern "C" void kernel_launch(void* const* d_in, const int* in_sizes, int n_in,
                              void* d_out, int out_size) {
    const int*   p_idx = (const int*)d_in[0];
    const int*   h_idx = (const int*)d_in[1];
    const float* emb   = (const float*)d_in[2];
    const float* W_a1  = (const float*)d_in[3];
    const float* b_a1  = (const float*)d_in[4];
    const float* W_a2  = (const float*)d_in[5];
    const float* b_a2  = (const float*)d_in[6];
    const float* W_c1  = (const float*)d_in[7];
    const float* b_c1  = (const float*)d_in[8];
    const float* W_c2  = (const float*)d_in[9];
    const float* b_c2  = (const float*)d_in[10];
    const float* W_g1  = (const float*)d_in[11];
    const float* b_g1  = (const float*)d_in[12];
    const float* W_g2  = (const float*)d_in[13];
    const float* b_g2  = (const float*)d_in[14];
    const float* W_g3  = (const float*)d_in[15];
    const float* b_g3  = (const float*)d_in[16];

    float* out      = (float*)d_out;
    float* outE     = out;
    float* outBeta  = outE + (size_t)LPn * LHn;
    float* outAlpha = outBeta + (size_t)LPn * Dn;
    float* outV     = outAlpha + (size_t)LHn * Dn;
    float* outY     = outV + 2 * Hn;

    float *embp, *t1, *fa, *t2, *cat, *part, *eik, *ekj, *v;
    float *wa1, *wa2, *wc1, *wc2;
    cudaGetSymbolAddress((void**)&embp, g_emb);
    cudaGetSymbolAddress((void**)&t1, g_t1);
    cudaGetSymbolAddress((void**)&fa, g_fa);
    cudaGetSymbolAddress((void**)&t2, g_t2);
    cudaGetSymbolAddress((void**)&cat, g_cat);
    cudaGetSymbolAddress((void**)&part, g_part);
    cudaGetSymbolAddress((void**)&eik, g_eik);
    cudaGetSymbolAddress((void**)&ekj, g_ekj);
    cudaGetSymbolAddress((void**)&v, g_v);
    cudaGetSymbolAddress((void**)&wa1, g_wa1);
    cudaGetSymbolAddress((void**)&wa2, g_wa2);
    cudaGetSymbolAddress((void**)&wc1, g_wc1);
    cudaGetSymbolAddress((void**)&wc2, g_wc2);

    const int SM_DD = smem_bytes(false, false);
    const int SM_DT = smem_bytes(false, true);
    const int SM_TT = smem_bytes(true, true);
    cudaFuncSetAttribute(tgemm<false, false, 1, true, false>,  cudaFuncAttributeMaxDynamicSharedMemorySize, SM_DD);
    cudaFuncSetAttribute(tgemm<false, false, 1, false, false>, cudaFuncAttributeMaxDynamicSharedMemorySize, SM_DD);
    cudaFuncSetAttribute(tgemm<false, true, 0, true, false>,   cudaFuncAttributeMaxDynamicSharedMemorySize, SM_DT);
    cudaFuncSetAttribute(tgemm<false, true, 0, false, true>,   cudaFuncAttributeMaxDynamicSharedMemorySize, SM_DT);
    cudaFuncSetAttribute(tgemm<true, true, 0, false, true>,    cudaFuncAttributeMaxDynamicSharedMemorySize, SM_TT);

    const int TB = 256;
    const int MT = LPn + LHn;  // 8192

    // gathers (rounded), weight conversion, zero accumulators
    gather4_k<<<(LPn * (Dn / 4) + TB - 1) / TB, TB>>>(p_idx, emb, embp, LPn);
    gather4_k<<<(LHn * (Dn / 4) + TB - 1) / TB, TB>>>(h_idx, emb, embp + (size_t)LPn * Dn, LHn);
    cvtw_k<<<(Hn * Dn + TB - 1) / TB, TB>>>(W_a1, wa1, Hn * Dn);
    cvtw_k<<<(Hn * Hn + TB - 1) / TB, TB>>>(W_a2, wa2, Hn * Hn);
    cvtw_k<<<(Hn * 2 * Dn + TB - 1) / TB, TB>>>(W_c1, wc1, Hn * 2 * Dn);
    cvtw_k<<<(Hn * Hn + TB - 1) / TB, TB>>>(W_c2, wc2, Hn * Hn);
    zero_k<<<16, 256>>>();

    // attend (merged p|h)
    tgemm<false, false, 1, true, false><<<dim3(Hn / 128, MT / 128), 256, SM_DD>>>(
        embp, Dn, wa1, Dn, b_a1, t1, Hn, MT, Hn, Dn, 0);
    tgemm<false, false, 1, true, false><<<dim3(Hn / 128, MT / 128), 256, SM_DD>>>(
        t1, Hn, wa2, Hn, b_a2, fa, Hn, MT, Hn, Hn, 0);

    // E = fp @ reshape(fh,[H,LH]) (rounded output)
    tgemm<false, true, 0, true, false><<<dim3(LHn / 128, LPn / 128), 256, SM_DT>>>(
        fa, Hn, fa + (size_t)LPn * Hn, LHn, nullptr, outE, LHn, LPn, LHn, Hn, 0);

    rowsum_k<<<LPn / 8, 256>>>(outE, eik);
    colsum_acc_k<<<dim3(LHn / 256, 32), 256>>>(outE, ekj, LHn, LPn / 32);

    // beta partials (split-K), then reduce + 1/eik
    tgemm<false, true, 0, false, true>
        <<<dim3((Dn + 127) / 128, LPn / 128, NSPLIT), 256, SM_DT>>>(
        outE, LHn, embp + (size_t)LPn * Dn, Dn, nullptr, part, Dn,
        LPn, Dn, LHn, LHn / NSPLIT);
    reduce_scale_k<<<(LPn * Dn / 4 + TB - 1) / TB, TB>>>(part, eik, outBeta, LPn, Dn);

    // alpha partials (split-K, A = E^T), then reduce + 1/ekj
    tgemm<true, true, 0, false, true>
        <<<dim3((Dn + 127) / 128, LHn / 128, NSPLIT), 256, SM_TT>>>(
        outE, LHn, embp, Dn, nullptr, part, Dn,
        LHn, Dn, LPn, LPn / NSPLIT);
    reduce_scale_k<<<(LHn * Dn / 4 + TB - 1) / TB, TB>>>(part, ekj, outAlpha, LHn, Dn);

    // comp (merged)
    concat_k<<<(MT * (2 * Dn / 4) + TB - 1) / TB, TB>>>(outBeta, outAlpha, cat);
    tgemm<false, false, 1, true, false><<<dim3(Hn / 128, MT / 128), 256, SM_DD>>>(
        cat, 2 * Dn, wc1, 2 * Dn, b_c1, t1, Hn, MT, Hn, 2 * Dn, 0);
    tgemm<false, false, 1, false, false><<<dim3(Hn / 128, MT / 128), 256, SM_DD>>>(
        t1, Hn, wc2, Hn, b_c2, t2, Hn, MT, Hn, Hn, 0);
    colsum_acc_k<<<dim3(Hn / 256, 32), 256>>>(t2, v, Hn, LPn / 32);
    colsum_acc_k<<<dim3(Hn / 256, 32), 256>>>(t2 + (size_t)LPn * Hn, v + Hn, Hn, LHn / 32);

    final_k<<<1, 1024>>>(W_g1, b_g1, W_g2, b_g2, W_g3, b_g3, outV, outY);
}